// round 6
// baseline (speedup 1.0000x reference)
#include <cuda_runtime.h>
#include <cstdint>

#define LSEQ  65536
#define HEADS 8
#define DIM   32
#define BS    128
#define NB    (LSEQ / BS)

#define QK_STRIDE 40   // floats; float2 fragment loads run at full crossbar rate
#define V_STRIDE  36   // floats; scalar PV B-loads conflict-free
#define SMEM_FLOATS (2 * 128 * QK_STRIDE + 128 * V_STRIDE)
#define SMEM_BYTES  (SMEM_FLOATS * 4)

// 1/sqrt(32) * log2(e): QK scores come out in the exp2 domain
#define SCALE_LOG2E ((float)(0.17677669529663687 * 1.4426950408889634))

__device__ __forceinline__ uint32_t f2tf(float x) {
    uint32_t u;
    asm("cvt.rna.tf32.f32 %0, %1;" : "=r"(u) : "f"(x));
    return u;
}

__device__ __forceinline__ float ex2(float x) {
    float r;
    asm("ex2.approx.ftz.f32 %0, %1;" : "=f"(r) : "f"(x));
    return r;
}

__device__ __forceinline__ void mma_tf32(float* d,
                                         uint32_t a0, uint32_t a1, uint32_t a2, uint32_t a3,
                                         uint32_t b0, uint32_t b1) {
    asm volatile("mma.sync.aligned.m16n8k8.row.col.f32.tf32.tf32.f32 "
                 "{%0,%1,%2,%3}, {%4,%5,%6,%7}, {%8,%9}, {%0,%1,%2,%3};"
                 : "+f"(d[0]), "+f"(d[1]), "+f"(d[2]), "+f"(d[3])
                 : "r"(a0), "r"(a1), "r"(a2), "r"(a3), "r"(b0), "r"(b1));
}

__global__ void __launch_bounds__(256, 3)
bucket_attn_kernel(const float* __restrict__ Q, const float* __restrict__ K,
                   const float* __restrict__ V, const int* __restrict__ scope,
                   float* __restrict__ O) {
    extern __shared__ float smem[];
    float* Qs = smem;                       // [128][40]
    float* Ks = Qs + 128 * QK_STRIDE;       // [128][40]
    float* Vs = Ks + 128 * QK_STRIDE;       // [128][36]  natural [key][d]

    const int bucket = blockIdx.x;
    const int h      = blockIdx.y;
    const int b      = blockIdx.z;
    const int tid    = threadIdx.x;

    const int sidx = (b * NB + bucket) * 2;
    const int lo = scope[sidx]     - bucket * BS;
    const int hi = scope[sidx + 1] - bucket * BS;
    const bool full = (lo <= 0) && (hi >= BS);   // uniform per CTA

    const size_t base = ((size_t)(b * LSEQ + bucket * BS) * HEADS + h) * DIM;
    const float4* Qg = (const float4*)(Q + base);
    const float4* Kg = (const float4*)(K + base);
    const float4* Vg = (const float4*)(V + base);
    const int rs4 = HEADS * DIM / 4;  // 64 float4 between rows

    // ---- Stage Q,K,V into SMEM (tf32-rounded; Q pre-scaled into exp2 domain) ----
    #pragma unroll
    for (int it = 0; it < 4; it++) {
        int idx = tid + it * 256;        // 0..1023 (128 rows x 8 float4)
        int row = idx >> 3, c4 = idx & 7;
        float4 q = Qg[row * rs4 + c4];
        float4 k = Kg[row * rs4 + c4];
        float4 v = Vg[row * rs4 + c4];
        uint4 qt = make_uint4(f2tf(q.x * SCALE_LOG2E), f2tf(q.y * SCALE_LOG2E),
                              f2tf(q.z * SCALE_LOG2E), f2tf(q.w * SCALE_LOG2E));
        uint4 kt = make_uint4(f2tf(k.x), f2tf(k.y), f2tf(k.z), f2tf(k.w));
        uint4 vt = make_uint4(f2tf(v.x), f2tf(v.y), f2tf(v.z), f2tf(v.w));
        *(uint4*)(Qs + row * QK_STRIDE + c4 * 4) = qt;
        *(uint4*)(Ks + row * QK_STRIDE + c4 * 4) = kt;
        *(uint4*)(Vs + row * V_STRIDE  + c4 * 4) = vt;
    }
    __syncthreads();

    const int lane = tid & 31;
    const int w    = tid >> 5;
    const int gid  = lane >> 2;     // 0..7
    const int tig  = lane & 3;      // 0..3
    const int r0   = w * 16 + gid;  // this lane's rows: r0 and r0+8

    float oacc[4][4];
    #pragma unroll
    for (int nt = 0; nt < 4; nt++)
        #pragma unroll
        for (int j = 0; j < 4; j++) oacc[nt][j] = 0.f;
    float m0 = -1e30f, m1 = -1e30f, l0 = 0.f, l1 = 0.f;

    // ==== two 64-column halves, online softmax in exp2 domain ====
    #pragma unroll
    for (int half = 0; half < 2; half++) {
        const int cb = half * 64;

        // ---- QK^T for this half: scores[16 rows][64 cols] ----
        float sacc[8][4];
        #pragma unroll
        for (int ct = 0; ct < 8; ct++)
            #pragma unroll
            for (int j = 0; j < 4; j++) sacc[ct][j] = 0.f;

        #pragma unroll
        for (int ks = 0; ks < 4; ks++) {
            int kc = ks * 8 + 2 * tig;
            float2 alo = *(const float2*)(Qs + r0 * QK_STRIDE + kc);        // (a0, a2)
            float2 ahi = *(const float2*)(Qs + (r0 + 8) * QK_STRIDE + kc);  // (a1, a3)
            uint32_t a0 = __float_as_uint(alo.x), a2 = __float_as_uint(alo.y);
            uint32_t a1 = __float_as_uint(ahi.x), a3 = __float_as_uint(ahi.y);
            #pragma unroll
            for (int ct = 0; ct < 8; ct++) {
                int kr = cb + ct * 8 + gid;
                float2 bp = *(const float2*)(Ks + kr * QK_STRIDE + kc);     // (b0, b1)
                mma_tf32(sacc[ct], a0, a1, a2, a3,
                         __float_as_uint(bp.x), __float_as_uint(bp.y));
            }
        }

        // ---- half max ----
        float h0 = -1e30f, h1 = -1e30f;
        if (full) {
            #pragma unroll
            for (int ct = 0; ct < 8; ct++) {
                h0 = fmaxf(h0, fmaxf(sacc[ct][0], sacc[ct][1]));
                h1 = fmaxf(h1, fmaxf(sacc[ct][2], sacc[ct][3]));
            }
        } else {
            #pragma unroll
            for (int ct = 0; ct < 8; ct++) {
                int c = cb + ct * 8 + 2 * tig;
                bool v0 = (c >= lo) && (c < hi);
                bool v1 = (c + 1 >= lo) && (c + 1 < hi);
                if (v0) { h0 = fmaxf(h0, sacc[ct][0]); h1 = fmaxf(h1, sacc[ct][2]); }
                if (v1) { h0 = fmaxf(h0, sacc[ct][1]); h1 = fmaxf(h1, sacc[ct][3]); }
            }
        }
        h0 = fmaxf(h0, __shfl_xor_sync(0xffffffffu, h0, 1));
        h0 = fmaxf(h0, __shfl_xor_sync(0xffffffffu, h0, 2));
        h1 = fmaxf(h1, __shfl_xor_sync(0xffffffffu, h1, 1));
        h1 = fmaxf(h1, __shfl_xor_sync(0xffffffffu, h1, 2));

        // ---- running max update + rescale ----
        float nm0 = fmaxf(m0, h0), nm1 = fmaxf(m1, h1);
        float rs0 = ex2(m0 - nm0), rs1 = ex2(m1 - nm1);
        m0 = nm0; m1 = nm1;

        float p0 = 0.f, p1 = 0.f;
        if (full) {
            #pragma unroll
            for (int ct = 0; ct < 8; ct++) {
                float e0 = ex2(sacc[ct][0] - m0);
                float e1 = ex2(sacc[ct][1] - m0);
                float e2 = ex2(sacc[ct][2] - m1);
                float e3 = ex2(sacc[ct][3] - m1);
                p0 += e0 + e1;
                p1 += e2 + e3;
                sacc[ct][0] = __uint_as_float(f2tf(e0));
                sacc[ct][1] = __uint_as_float(f2tf(e1));
                sacc[ct][2] = __uint_as_float(f2tf(e2));
                sacc[ct][3] = __uint_as_float(f2tf(e3));
            }
        } else {
            #pragma unroll
            for (int ct = 0; ct < 8; ct++) {
                int c = cb + ct * 8 + 2 * tig;
                bool v0 = (c >= lo) && (c < hi);
                bool v1 = (c + 1 >= lo) && (c + 1 < hi);
                float e0 = v0 ? ex2(sacc[ct][0] - m0) : 0.f;
                float e1 = v1 ? ex2(sacc[ct][1] - m0) : 0.f;
                float e2 = v0 ? ex2(sacc[ct][2] - m1) : 0.f;
                float e3 = v1 ? ex2(sacc[ct][3] - m1) : 0.f;
                p0 += e0 + e1;
                p1 += e2 + e3;
                sacc[ct][0] = __uint_as_float(f2tf(e0));
                sacc[ct][1] = __uint_as_float(f2tf(e1));
                sacc[ct][2] = __uint_as_float(f2tf(e2));
                sacc[ct][3] = __uint_as_float(f2tf(e3));
            }
        }
        p0 += __shfl_xor_sync(0xffffffffu, p0, 1);
        p0 += __shfl_xor_sync(0xffffffffu, p0, 2);
        p1 += __shfl_xor_sync(0xffffffffu, p1, 1);
        p1 += __shfl_xor_sync(0xffffffffu, p1, 2);
        l0 = l0 * rs0 + p0;
        l1 = l1 * rs1 + p1;

        #pragma unroll
        for (int nt = 0; nt < 4; nt++) {
            oacc[nt][0] *= rs0; oacc[nt][1] *= rs0;
            oacc[nt][2] *= rs1; oacc[nt][3] *= rs1;
        }

        // ---- P @ V for this half (C->A layout via k-permutation on V rows) ----
        #pragma unroll
        for (int kt = 0; kt < 8; kt++) {
            int key0 = cb + kt * 8 + 2 * tig;
            uint32_t a0 = __float_as_uint(sacc[kt][0]);
            uint32_t a1 = __float_as_uint(sacc[kt][2]);
            uint32_t a2 = __float_as_uint(sacc[kt][1]);
            uint32_t a3 = __float_as_uint(sacc[kt][3]);
            const float* v0p = Vs + key0 * V_STRIDE + gid;
            const float* v1p = v0p + V_STRIDE;
            #pragma unroll
            for (int nt = 0; nt < 4; nt++) {
                uint32_t b0 = __float_as_uint(v0p[nt * 8]);
                uint32_t b1 = __float_as_uint(v1p[nt * 8]);
                mma_tf32(oacc[nt], a0, a1, a2, a3, b0, b1);
            }
        }
    }

    // ---- normalize, mask invalid queries, write out ----
    float s0 = ((r0 >= lo) && (r0 < hi) && l0 > 0.f)         ? __frcp_rn(l0) : 0.f;
    float s1 = ((r0 + 8 >= lo) && (r0 + 8 < hi) && l1 > 0.f) ? __frcp_rn(l1) : 0.f;
    float* O0 = O + base + (size_t)r0 * (HEADS * DIM);
    float* O1 = O + base + (size_t)(r0 + 8) * (HEADS * DIM);
    #pragma unroll
    for (int nt = 0; nt < 4; nt++) {
        int c = nt * 8 + 2 * tig;
        *(float2*)(O0 + c) = make_float2(oacc[nt][0] * s0, oacc[nt][1] * s0);
        *(float2*)(O1 + c) = make_float2(oacc[nt][2] * s1, oacc[nt][3] * s1);
    }
}

extern "C" void kernel_launch(void* const* d_in, const int* in_sizes, int n_in,
                              void* d_out, int out_size) {
    const float* Q     = (const float*)d_in[0];
    const float* K     = (const float*)d_in[1];
    const float* V     = (const float*)d_in[2];
    const int*   scope = (const int*)d_in[3];
    (void)n_in; (void)out_size;

    int B = in_sizes[0] / (LSEQ * HEADS * DIM);  // = 2

    cudaFuncSetAttribute(bucket_attn_kernel,
                         cudaFuncAttributeMaxDynamicSharedMemorySize, SMEM_BYTES);
    cudaFuncSetAttribute(bucket_attn_kernel,
                         cudaFuncAttributePreferredSharedMemoryCarveout, 100);

    dim3 grid(NB, HEADS, B);
    bucket_attn_kernel<<<grid, 256, SMEM_BYTES>>>(Q, K, V, scope, (float*)d_out);
}

// round 7
// speedup vs baseline: 1.0770x; 1.0770x over previous
#include <cuda_runtime.h>
#include <cstdint>

#define LSEQ  65536
#define HEADS 8
#define DIM   32
#define BS    128
#define NB    (LSEQ / BS)

#define QK_STRIDE 40   // floats; float2 fragment loads at full crossbar rate
#define V_STRIDE  36   // floats; scalar/paired PV loads conflict-free
#define O_STRIDE  36

// float offsets in dynamic smem
#define OFF_Q   0
#define OFF_K   (128 * QK_STRIDE)
#define OFF_V   (2 * 128 * QK_STRIDE)
#define OFF_OB  (OFF_V + 128 * V_STRIDE)     // partial-O exchange [128][36]
#define OFF_MB  (OFF_OB + 128 * O_STRIDE)    // row max  [2][128]
#define OFF_LB  (OFF_MB + 256)               // row sum  [2][128]
#define SMEM_FLOATS (OFF_LB + 256)
#define SMEM_BYTES  (SMEM_FLOATS * 4)

// 1/sqrt(32) * log2(e): QK scores come out in the exp2 domain
#define SCALE_LOG2E ((float)(0.17677669529663687 * 1.4426950408889634))

__device__ __forceinline__ uint32_t f2tf(float x) {
    uint32_t u;
    asm("cvt.rna.tf32.f32 %0, %1;" : "=r"(u) : "f"(x));
    return u;
}

__device__ __forceinline__ float ex2(float x) {
    float r;
    asm("ex2.approx.ftz.f32 %0, %1;" : "=f"(r) : "f"(x));
    return r;
}

__device__ __forceinline__ void mma_tf32(float* d,
                                         uint32_t a0, uint32_t a1, uint32_t a2, uint32_t a3,
                                         uint32_t b0, uint32_t b1) {
    asm volatile("mma.sync.aligned.m16n8k8.row.col.f32.tf32.tf32.f32 "
                 "{%0,%1,%2,%3}, {%4,%5,%6,%7}, {%8,%9}, {%0,%1,%2,%3};"
                 : "+f"(d[0]), "+f"(d[1]), "+f"(d[2]), "+f"(d[3])
                 : "r"(a0), "r"(a1), "r"(a2), "r"(a3), "r"(b0), "r"(b1));
}

__global__ void __launch_bounds__(256, 2)
bucket_attn_kernel(const float* __restrict__ Q, const float* __restrict__ K,
                   const float* __restrict__ V, const int* __restrict__ scope,
                   float* __restrict__ O) {
    extern __shared__ float smem[];
    float* Qs   = smem + OFF_Q;
    float* Ks   = smem + OFF_K;
    float* Vs   = smem + OFF_V;
    float* obuf = smem + OFF_OB;
    float* mbuf = smem + OFF_MB;   // [side][row]
    float* lbuf = smem + OFF_LB;   // [side][row]

    const int bucket = blockIdx.x;
    const int h      = blockIdx.y;
    const int b      = blockIdx.z;
    const int tid    = threadIdx.x;

    const int sidx = (b * NB + bucket) * 2;
    const int lo = scope[sidx]     - bucket * BS;
    const int hi = scope[sidx + 1] - bucket * BS;
    const bool full = (lo <= 0) && (hi >= BS);   // uniform per CTA

    const size_t base = ((size_t)(b * LSEQ + bucket * BS) * HEADS + h) * DIM;
    const float4* Qg = (const float4*)(Q + base);
    const float4* Kg = (const float4*)(K + base);
    const float4* Vg = (const float4*)(V + base);
    const int rs4 = HEADS * DIM / 4;  // 64 float4 between rows

    // ---- Stage Q,K,V into SMEM (tf32-rounded; Q pre-scaled into exp2 domain) ----
    #pragma unroll
    for (int it = 0; it < 4; it++) {
        int idx = tid + it * 256;        // 0..1023 (128 rows x 8 float4)
        int row = idx >> 3, c4 = idx & 7;
        float4 q = Qg[row * rs4 + c4];
        float4 k = Kg[row * rs4 + c4];
        float4 v = Vg[row * rs4 + c4];
        uint4 qt = make_uint4(f2tf(q.x * SCALE_LOG2E), f2tf(q.y * SCALE_LOG2E),
                              f2tf(q.z * SCALE_LOG2E), f2tf(q.w * SCALE_LOG2E));
        uint4 kt = make_uint4(f2tf(k.x), f2tf(k.y), f2tf(k.z), f2tf(k.w));
        uint4 vt = make_uint4(f2tf(v.x), f2tf(v.y), f2tf(v.z), f2tf(v.w));
        *(uint4*)(Qs + row * QK_STRIDE + c4 * 4) = qt;
        *(uint4*)(Ks + row * QK_STRIDE + c4 * 4) = kt;
        *(uint4*)(Vs + row * V_STRIDE  + c4 * 4) = vt;
    }
    __syncthreads();

    const int lane = tid & 31;
    const int w    = tid >> 5;
    const int gid  = lane >> 2;     // 0..7
    const int tig  = lane & 3;      // 0..3
    const int s    = w >> 2;        // key side: 0 -> keys [0,64), 1 -> [64,128)
    const int pi   = w & 3;         // pair index -> q-rows [32pi, 32pi+32)
    const int kb   = s * 64;
    const int r0   = pi * 32 + gid; // lane rows: r0, r0+8 (tile0); r0+16, r0+24 (tile1)

    // ---- QK^T : scores[2 tiles][8 key-tiles][4], 64 keys per side ----
    float sacc[2][8][4];
    #pragma unroll
    for (int t = 0; t < 2; t++)
        #pragma unroll
        for (int ct = 0; ct < 8; ct++)
            #pragma unroll
            for (int j = 0; j < 4; j++) sacc[t][ct][j] = 0.f;

    #pragma unroll
    for (int ks = 0; ks < 4; ks++) {
        int kc = ks * 8 + 2 * tig;
        float2 a00 = *(const float2*)(Qs + (r0     ) * QK_STRIDE + kc);  // (a0,a2) t0
        float2 a01 = *(const float2*)(Qs + (r0 +  8) * QK_STRIDE + kc);  // (a1,a3) t0
        float2 a10 = *(const float2*)(Qs + (r0 + 16) * QK_STRIDE + kc);  // t1
        float2 a11 = *(const float2*)(Qs + (r0 + 24) * QK_STRIDE + kc);
        #pragma unroll
        for (int ct = 0; ct < 8; ct++) {
            float2 bp = *(const float2*)(Ks + (kb + ct * 8 + gid) * QK_STRIDE + kc);
            uint32_t b0 = __float_as_uint(bp.x), b1 = __float_as_uint(bp.y);
            mma_tf32(sacc[0][ct], __float_as_uint(a00.x), __float_as_uint(a01.x),
                     __float_as_uint(a00.y), __float_as_uint(a01.y), b0, b1);
            mma_tf32(sacc[1][ct], __float_as_uint(a10.x), __float_as_uint(a11.x),
                     __float_as_uint(a10.y), __float_as_uint(a11.y), b0, b1);
        }
    }

    // ---- per-side row max over this side's 64 keys ----
    float hm[2][2] = {{-1e30f, -1e30f}, {-1e30f, -1e30f}};  // [tile][rowhalf]
    if (full) {
        #pragma unroll
        for (int t = 0; t < 2; t++)
            #pragma unroll
            for (int ct = 0; ct < 8; ct++) {
                hm[t][0] = fmaxf(hm[t][0], fmaxf(sacc[t][ct][0], sacc[t][ct][1]));
                hm[t][1] = fmaxf(hm[t][1], fmaxf(sacc[t][ct][2], sacc[t][ct][3]));
            }
    } else {
        #pragma unroll
        for (int t = 0; t < 2; t++)
            #pragma unroll
            for (int ct = 0; ct < 8; ct++) {
                int c = kb + ct * 8 + 2 * tig;
                bool v0 = (c >= lo) && (c < hi);
                bool v1 = (c + 1 >= lo) && (c + 1 < hi);
                if (v0) { hm[t][0] = fmaxf(hm[t][0], sacc[t][ct][0]);
                          hm[t][1] = fmaxf(hm[t][1], sacc[t][ct][2]); }
                if (v1) { hm[t][0] = fmaxf(hm[t][0], sacc[t][ct][1]);
                          hm[t][1] = fmaxf(hm[t][1], sacc[t][ct][3]); }
            }
    }
    #pragma unroll
    for (int t = 0; t < 2; t++)
        #pragma unroll
        for (int rh = 0; rh < 2; rh++) {
            hm[t][rh] = fmaxf(hm[t][rh], __shfl_xor_sync(0xffffffffu, hm[t][rh], 1));
            hm[t][rh] = fmaxf(hm[t][rh], __shfl_xor_sync(0xffffffffu, hm[t][rh], 2));
        }
    if (tig == 0) {
        mbuf[s * 128 + r0]      = hm[0][0];
        mbuf[s * 128 + r0 + 8]  = hm[0][1];
        mbuf[s * 128 + r0 + 16] = hm[1][0];
        mbuf[s * 128 + r0 + 24] = hm[1][1];
    }
    __syncthreads();

    float m[2][2];
    #pragma unroll
    for (int t = 0; t < 2; t++)
        #pragma unroll
        for (int rh = 0; rh < 2; rh++) {
            int row = r0 + 16 * t + 8 * rh;
            m[t][rh] = fmaxf(mbuf[row], mbuf[128 + row]);
        }

    // ---- exp (combined max) + per-side partial sums ----
    float pl[2][2] = {{0.f, 0.f}, {0.f, 0.f}};
    if (full) {
        #pragma unroll
        for (int t = 0; t < 2; t++)
            #pragma unroll
            for (int ct = 0; ct < 8; ct++) {
                float e0 = ex2(sacc[t][ct][0] - m[t][0]);
                float e1 = ex2(sacc[t][ct][1] - m[t][0]);
                float e2 = ex2(sacc[t][ct][2] - m[t][1]);
                float e3 = ex2(sacc[t][ct][3] - m[t][1]);
                pl[t][0] += e0 + e1;
                pl[t][1] += e2 + e3;
                sacc[t][ct][0] = __uint_as_float(f2tf(e0));
                sacc[t][ct][1] = __uint_as_float(f2tf(e1));
                sacc[t][ct][2] = __uint_as_float(f2tf(e2));
                sacc[t][ct][3] = __uint_as_float(f2tf(e3));
            }
    } else {
        #pragma unroll
        for (int t = 0; t < 2; t++)
            #pragma unroll
            for (int ct = 0; ct < 8; ct++) {
                int c = kb + ct * 8 + 2 * tig;
                bool v0 = (c >= lo) && (c < hi);
                bool v1 = (c + 1 >= lo) && (c + 1 < hi);
                float e0 = v0 ? ex2(sacc[t][ct][0] - m[t][0]) : 0.f;
                float e1 = v1 ? ex2(sacc[t][ct][1] - m[t][0]) : 0.f;
                float e2 = v0 ? ex2(sacc[t][ct][2] - m[t][1]) : 0.f;
                float e3 = v1 ? ex2(sacc[t][ct][3] - m[t][1]) : 0.f;
                pl[t][0] += e0 + e1;
                pl[t][1] += e2 + e3;
                sacc[t][ct][0] = __uint_as_float(f2tf(e0));
                sacc[t][ct][1] = __uint_as_float(f2tf(e1));
                sacc[t][ct][2] = __uint_as_float(f2tf(e2));
                sacc[t][ct][3] = __uint_as_float(f2tf(e3));
            }
    }
    #pragma unroll
    for (int t = 0; t < 2; t++)
        #pragma unroll
        for (int rh = 0; rh < 2; rh++) {
            pl[t][rh] += __shfl_xor_sync(0xffffffffu, pl[t][rh], 1);
            pl[t][rh] += __shfl_xor_sync(0xffffffffu, pl[t][rh], 2);
        }
    if (tig == 0) {
        lbuf[s * 128 + r0]      = pl[0][0];
        lbuf[s * 128 + r0 + 8]  = pl[0][1];
        lbuf[s * 128 + r0 + 16] = pl[1][0];
        lbuf[s * 128 + r0 + 24] = pl[1][1];
    }

    // ---- P @ V over this side's 64 keys; B fragments shared by both row tiles ----
    float oacc[2][4][4];
    #pragma unroll
    for (int t = 0; t < 2; t++)
        #pragma unroll
        for (int nt = 0; nt < 4; nt++)
            #pragma unroll
            for (int j = 0; j < 4; j++) oacc[t][nt][j] = 0.f;

    #pragma unroll
    for (int kt = 0; kt < 8; kt++) {
        int key0 = kb + kt * 8 + 2 * tig;
        const float* v0p = Vs + key0 * V_STRIDE + gid;
        const float* v1p = v0p + V_STRIDE;
        #pragma unroll
        for (int nt = 0; nt < 4; nt++) {
            uint32_t b0 = __float_as_uint(v0p[nt * 8]);
            uint32_t b1 = __float_as_uint(v1p[nt * 8]);
            #pragma unroll
            for (int t = 0; t < 2; t++) {
                mma_tf32(oacc[t][nt],
                         __float_as_uint(sacc[t][kt][0]), __float_as_uint(sacc[t][kt][2]),
                         __float_as_uint(sacc[t][kt][1]), __float_as_uint(sacc[t][kt][3]),
                         b0, b1);
            }
        }
    }
    __syncthreads();   // lbuf complete; obuf region free for exchange

    // ---- exchange: side 1 posts partial O; side 0 sums, normalizes, stores ----
    if (s == 1) {
        #pragma unroll
        for (int t = 0; t < 2; t++) {
            int rt = r0 + 16 * t;
            #pragma unroll
            for (int nt = 0; nt < 4; nt++) {
                int c = nt * 8 + 2 * tig;
                *(float2*)(obuf + rt * O_STRIDE + c) =
                    make_float2(oacc[t][nt][0], oacc[t][nt][1]);
                *(float2*)(obuf + (rt + 8) * O_STRIDE + c) =
                    make_float2(oacc[t][nt][2], oacc[t][nt][3]);
            }
        }
    }
    __syncthreads();

    if (s == 0) {
        #pragma unroll
        for (int t = 0; t < 2; t++) {
            int rt = r0 + 16 * t;
            float lA = lbuf[rt] + lbuf[128 + rt];
            float lB = lbuf[rt + 8] + lbuf[128 + rt + 8];
            float sA = ((rt >= lo) && (rt < hi) && lA > 0.f)         ? __frcp_rn(lA) : 0.f;
            float sB = ((rt + 8 >= lo) && (rt + 8 < hi) && lB > 0.f) ? __frcp_rn(lB) : 0.f;
            float* OA = O + base + (size_t)rt * (HEADS * DIM);
            float* OB = OA + 8 * (HEADS * DIM);
            #pragma unroll
            for (int nt = 0; nt < 4; nt++) {
                int c = nt * 8 + 2 * tig;
                float2 pA = *(const float2*)(obuf + rt * O_STRIDE + c);
                float2 pB = *(const float2*)(obuf + (rt + 8) * O_STRIDE + c);
                *(float2*)(OA + c) = make_float2((oacc[t][nt][0] + pA.x) * sA,
                                                 (oacc[t][nt][1] + pA.y) * sA);
                *(float2*)(OB + c) = make_float2((oacc[t][nt][2] + pB.x) * sB,
                                                 (oacc[t][nt][3] + pB.y) * sB);
            }
        }
    }
}

extern "C" void kernel_launch(void* const* d_in, const int* in_sizes, int n_in,
                              void* d_out, int out_size) {
    const float* Q     = (const float*)d_in[0];
    const float* K     = (const float*)d_in[1];
    const float* V     = (const float*)d_in[2];
    const int*   scope = (const int*)d_in[3];
    (void)n_in; (void)out_size;

    int B = in_sizes[0] / (LSEQ * HEADS * DIM);  // = 2

    cudaFuncSetAttribute(bucket_attn_kernel,
                         cudaFuncAttributeMaxDynamicSharedMemorySize, SMEM_BYTES);

    dim3 grid(NB, HEADS, B);
    bucket_attn_kernel<<<grid, 256, SMEM_BYTES>>>(Q, K, V, scope, (float*)d_out);
}